// round 5
// baseline (speedup 1.0000x reference)
#include <cuda_runtime.h>
#include <cstddef>

#define NW    100000
#define VD    128
#define BATCH 16384
#define KNUM  26
#define NPAIR ((KNUM + 1) / 2)   // 13 k-pairs
#define NPW   4                  // max pairs per warp (wid + 4*i)

// 51.2 MB transposed copy of O: OT[word][v]. Static device scratch (no alloc).
__device__ float g_OT[(size_t)NW * VD];

// ---------------------------------------------------------------------------
// Kernel 1: transpose O [VD, NW] -> OT [NW, VD], tiled 32x32 via smem.
// Reads: scalar, coalesced along w. Writes: float4 (STG.128) along v.
// ---------------------------------------------------------------------------
__global__ void transpose_kernel(const float* __restrict__ O) {
    __shared__ float tile[32][33];  // +1 pad
    const int w0 = blockIdx.x * 32;
    const int v0 = blockIdx.y * 32;
    const int t  = threadIdx.x;
    const int tx = t & 31;
    const int ty = t >> 5;

#pragma unroll
    for (int j = 0; j < 32; j += 8) {
        tile[ty + j][tx] = O[(size_t)(v0 + ty + j) * NW + (w0 + tx)];
    }
    __syncthreads();

    const int wl = t >> 3;          // 0..31
    const int vc = t & 7;           // 0..7
    float4 o;
    o.x = tile[4 * vc + 0][wl];
    o.y = tile[4 * vc + 1][wl];
    o.z = tile[4 * vc + 2][wl];
    o.w = tile[4 * vc + 3][wl];
    *reinterpret_cast<float4*>(g_OT + (size_t)(w0 + wl) * VD + v0 + 4 * vc) = o;
}

// ---------------------------------------------------------------------------
// Kernel 2: one block (128 threads = 4 warps) per batch element b.
// Half-warp layout: lanes 0-15 own k=2p, lanes 16-31 own k=2p+1.
// Each lane covers 8 v-elements (2 x float4), so the cross-lane reduce is
// 4 shuffles shared by TWO scores (vs 5 shuffles per score before).
// Pair-level prefetch pipeline hides the L2-hit latency of the next rows.
// ---------------------------------------------------------------------------
__global__ __launch_bounds__(VD)
void score_kernel(const int* __restrict__ doc_ids,
                  const int* __restrict__ tnids,
                  const float* __restrict__ D,
                  float* __restrict__ out) {
    const int b    = blockIdx.x;
    const int t    = threadIdx.x;
    const int lane = t & 31;
    const int wid  = t >> 5;
    const int half = lane >> 4;     // 0: k=2p, 1: k=2p+1
    const int sub  = lane & 15;     // covers v = 8*sub .. 8*sub+7

    __shared__ __align__(16) float sd[VD];
    __shared__ int swords[KNUM];

    const int doc = __ldg(&doc_ids[b]);
    sd[t] = D[(size_t)doc * VD + t];
    if (t < KNUM) swords[t] = __ldg(&tnids[b * KNUM + t]);
    __syncthreads();

    const float4 dva = reinterpret_cast<const float4*>(sd)[2 * sub];
    const float4 dvb = reinterpret_cast<const float4*>(sd)[2 * sub + 1];

    // prologue: load rows for pair p = wid
    int p = wid;
    float4 ca, cb;
    {
        const int k = 2 * p + half;            // p = wid < 13 always
        const float4* row = reinterpret_cast<const float4*>(
                                g_OT + (size_t)swords[k] * VD) + 2 * sub;
        ca = row[0];
        cb = row[1];
    }

#pragma unroll
    for (int i = 0; i < NPW; i++) {
        const int pn = p + 4;

        // prefetch next pair's rows
        float4 na, nb;
        if (pn < NPAIR) {
            const int kn = 2 * pn + half;
            const float4* row = reinterpret_cast<const float4*>(
                                    g_OT + (size_t)swords[kn] * VD) + 2 * sub;
            na = row[0];
            nb = row[1];
        }

        if (p < NPAIR) {
            float s0 = dva.x * ca.x + dva.y * ca.y + dva.z * ca.z + dva.w * ca.w;
            float s1 = dvb.x * cb.x + dvb.y * cb.y + dvb.z * cb.z + dvb.w * cb.w;
            float s  = s0 + s1;
            s += __shfl_xor_sync(0xffffffffu, s, 8);
            s += __shfl_xor_sync(0xffffffffu, s, 4);
            s += __shfl_xor_sync(0xffffffffu, s, 2);
            s += __shfl_xor_sync(0xffffffffu, s, 1);
            if (sub == 0) out[b * KNUM + 2 * p + half] = s;  // lanes 0 and 16
        }
        p  = pn;
        ca = na;
        cb = nb;
    }
}

// ---------------------------------------------------------------------------
// Inputs (metadata order): context_ids[B] i32 (unused), doc_ids[B] i32,
// target_noise_ids[B*K] i32, D[NUM_DOCS*VD] f32, O[VD*NW] f32.
// Output: out[B*K] f32.
// ---------------------------------------------------------------------------
extern "C" void kernel_launch(void* const* d_in, const int* in_sizes, int n_in,
                              void* d_out, int out_size) {
    const int*   doc_ids = (const int*)d_in[1];
    const int*   tnids   = (const int*)d_in[2];
    const float* D       = (const float*)d_in[3];
    const float* O       = (const float*)d_in[4];
    float*       out     = (float*)d_out;

    dim3 tg(NW / 32, VD / 32);
    transpose_kernel<<<tg, 256>>>(O);

    score_kernel<<<BATCH, VD>>>(doc_ids, tnids, D, out);
}

// round 6
// speedup vs baseline: 1.1974x; 1.1974x over previous
#include <cuda_runtime.h>
#include <cuda_fp16.h>
#include <cstddef>

#define NW    100000
#define VD    128
#define BATCH 16384
#define KNUM  26
#define NSLOT 7   // max k-slots per warp (wid + 4*i)

// Scratch (static device globals; no allocation):
//   g_OTh: 25.6 MB fp16 transposed O, OTh[word][v]
//   g_dg : 8 MB   fp32 gathered doc vectors, dg[b][v]
__device__ __half g_OTh[(size_t)NW * VD];
__device__ float  g_dg[(size_t)BATCH * VD];

// ---------------------------------------------------------------------------
// Kernel A: gather dg[b] = D[doc_ids[b]]  (one warp per b, float4 lanes).
// Pure gather: huge MLP, hides the doc->row dependent chain completely.
// ---------------------------------------------------------------------------
__global__ void gather_kernel(const int* __restrict__ doc_ids,
                              const float* __restrict__ D) {
    const int b    = blockIdx.x * 8 + (threadIdx.x >> 5);
    const int lane = threadIdx.x & 31;
    const int doc  = __ldg(&doc_ids[b]);
    const float4 v =
        __ldg(reinterpret_cast<const float4*>(D + (size_t)doc * VD) + lane);
    reinterpret_cast<float4*>(g_dg + (size_t)b * VD)[lane] = v;
}

// ---------------------------------------------------------------------------
// Kernel B: transpose O [VD, NW] f32 -> OTh [NW, VD] fp16, tiled 32x32.
// Read: float4 coalesced along w. Write: uint2 (4 halves) along v.
// Conflict-free smem via [32][33] pad (both phases verified bank-unique).
// ---------------------------------------------------------------------------
__global__ void transpose_kernel(const float* __restrict__ O) {
    __shared__ float tile[32][33];
    const int w0 = blockIdx.x * 32;
    const int v0 = blockIdx.y * 32;
    const int t  = threadIdx.x;

    // read phase: thread (ty = v_local, tx = w-float4-chunk)
    {
        const int ty = t >> 3;
        const int tx = t & 7;
        const float4 f = __ldg(reinterpret_cast<const float4*>(
                                   O + (size_t)(v0 + ty) * NW + w0) + tx);
        tile[ty][4 * tx + 0] = f.x;
        tile[ty][4 * tx + 1] = f.y;
        tile[ty][4 * tx + 2] = f.z;
        tile[ty][4 * tx + 3] = f.w;
    }
    __syncthreads();

    // write phase: thread (wl = w_local, vc = v-quad) -> 4 halves (8B)
    {
        const int wl = t >> 3;
        const int vc = t & 7;
        const __half2 p0 = __floats2half2_rn(tile[4 * vc + 0][wl],
                                             tile[4 * vc + 1][wl]);
        const __half2 p1 = __floats2half2_rn(tile[4 * vc + 2][wl],
                                             tile[4 * vc + 3][wl]);
        uint2 o;
        o.x = *reinterpret_cast<const unsigned*>(&p0);
        o.y = *reinterpret_cast<const unsigned*>(&p1);
        *reinterpret_cast<uint2*>(
            g_OTh + (size_t)(w0 + wl) * VD + v0 + 4 * vc) = o;
    }
}

// ---------------------------------------------------------------------------
// Kernel C: score. One block (128 thr = 4 warps) per b. No smem, no barriers.
// Warp wid owns k = wid+4i (7 predicated slots). All word ids + dv loaded
// up front (independent); OT rows software-pipelined (prefetch depth 1).
// Row load = LDG.64 of 4 halves per lane (256B/row = 2 L1 lines).
// ---------------------------------------------------------------------------
__global__ __launch_bounds__(VD)
void score_kernel(const int* __restrict__ tnids,
                  float* __restrict__ out) {
    const int b    = blockIdx.x;
    const int t    = threadIdx.x;
    const int lane = t & 31;
    const int wid  = t >> 5;

    // doc vector chunk: address depends only on (b, lane) -> fully independent
    const float4 dv =
        __ldg(reinterpret_cast<const float4*>(g_dg + (size_t)b * VD) + lane);

    // word ids (lane-uniform loads, batched)
    int words[NSLOT];
#pragma unroll
    for (int i = 0; i < NSLOT; i++) {
        const int k = wid + 4 * i;
        words[i] = (k < KNUM) ? __ldg(&tnids[b * KNUM + k]) : 0;
    }

    // prologue
    uint2 cur = *reinterpret_cast<const uint2*>(
                    g_OTh + (size_t)words[0] * VD + 4 * lane);

#pragma unroll
    for (int i = 0; i < NSLOT; i++) {
        const int k = wid + 4 * i;

        uint2 nxt;
        if (i + 1 < NSLOT && k + 4 < KNUM) {
            nxt = *reinterpret_cast<const uint2*>(
                      g_OTh + (size_t)words[i + 1] * VD + 4 * lane);
        }

        if (k < KNUM) {
            const __half2 h0 = *reinterpret_cast<const __half2*>(&cur.x);
            const __half2 h1 = *reinterpret_cast<const __half2*>(&cur.y);
            const float2 f0 = __half22float2(h0);
            const float2 f1 = __half22float2(h1);
            float s = dv.x * f0.x + dv.y * f0.y + dv.z * f1.x + dv.w * f1.y;
            s += __shfl_xor_sync(0xffffffffu, s, 16);
            s += __shfl_xor_sync(0xffffffffu, s, 8);
            s += __shfl_xor_sync(0xffffffffu, s, 4);
            s += __shfl_xor_sync(0xffffffffu, s, 2);
            s += __shfl_xor_sync(0xffffffffu, s, 1);
            if (lane == 0) out[b * KNUM + k] = s;
        }
        cur = nxt;
    }
}

// ---------------------------------------------------------------------------
// Inputs (metadata order): context_ids[B] i32 (unused), doc_ids[B] i32,
// target_noise_ids[B*K] i32, D[NUM_DOCS*VD] f32, O[VD*NW] f32.
// Output: out[B*K] f32.
// ---------------------------------------------------------------------------
extern "C" void kernel_launch(void* const* d_in, const int* in_sizes, int n_in,
                              void* d_out, int out_size) {
    const int*   doc_ids = (const int*)d_in[1];
    const int*   tnids   = (const int*)d_in[2];
    const float* D       = (const float*)d_in[3];
    const float* O       = (const float*)d_in[4];
    float*       out     = (float*)d_out;

    gather_kernel<<<BATCH / 8, 256>>>(doc_ids, D);

    dim3 tg(NW / 32, VD / 32);
    transpose_kernel<<<tg, 256>>>(O);

    score_kernel<<<BATCH, VD>>>(tnids, out);
}

// round 9
// speedup vs baseline: 1.2631x; 1.0548x over previous
#include <cuda_runtime.h>
#include <cuda_fp16.h>
#include <cstddef>

#define NW    100000
#define VD    128
#define BATCH 16384
#define KNUM  26
#define NSLOT 7    // max k-slots per warp (wid + 4*i)

#define GB     512                 // gather blocks (256 thr, 8 warps x 4 b)
#define TBX    (NW / 32)           // 3125
#define TBY    (VD / 32)           // 4
#define NBLK   (GB + TBX * TBY)    // fused grid

// Scratch (static device globals; no allocation):
//   g_OTh: 25.6 MB fp16 transposed O, OTh[word][v]
//   g_dg : 8 MB   fp32 gathered doc vectors, dg[b][v]
__device__ __half g_OTh[(size_t)NW * VD];
__device__ float  g_dg[(size_t)BATCH * VD];

// ---------------------------------------------------------------------------
// Kernel A (fused): blocks [0, GB) gather dg[b] = D[doc_ids[b]] with 4 b's
// per warp (MLP=4 on both the id loads and the row loads); blocks [GB, ...)
// transpose O [VD, NW] f32 -> OTh [NW, VD] fp16, tiled 32x32 via smem.
// Gather blocks lead the grid so they overlap the DRAM-bound transpose.
// ---------------------------------------------------------------------------
__global__ __launch_bounds__(256)
void prep_kernel(const int* __restrict__ doc_ids,
                 const float* __restrict__ D,
                 const float* __restrict__ O) {
    const int t = threadIdx.x;

    if (blockIdx.x < GB) {
        // ---- gather partition ----
        const int warp = t >> 5;
        const int lane = t & 31;
        const int b0   = (blockIdx.x * 8 + warp) * 4;

        int doc[4];
#pragma unroll
        for (int i = 0; i < 4; i++) doc[i] = __ldg(&doc_ids[b0 + i]);

        float4 v[4];
#pragma unroll
        for (int i = 0; i < 4; i++) {
            v[i] = __ldg(reinterpret_cast<const float4*>(
                             D + (size_t)doc[i] * VD) + lane);
        }
#pragma unroll
        for (int i = 0; i < 4; i++) {
            reinterpret_cast<float4*>(g_dg + (size_t)(b0 + i) * VD)[lane] = v[i];
        }
        return;
    }

    // ---- transpose partition ----
    const int idx = blockIdx.x - GB;
    const int w0  = (idx % TBX) * 32;
    const int v0  = (idx / TBX) * 32;

    __shared__ float tile[32][33];

    {   // read: thread (ty = v_local, tx = w-float4-chunk), coalesced along w
        const int ty = t >> 3;
        const int tx = t & 7;
        const float4 f = __ldg(reinterpret_cast<const float4*>(
                                   O + (size_t)(v0 + ty) * NW + w0) + tx);
        tile[ty][4 * tx + 0] = f.x;
        tile[ty][4 * tx + 1] = f.y;
        tile[ty][4 * tx + 2] = f.z;
        tile[ty][4 * tx + 3] = f.w;
    }
    __syncthreads();

    {   // write: thread (wl = w_local, vc = v-quad) -> 4 halves (8B)
        const int wl = t >> 3;
        const int vc = t & 7;
        const __half2 p0 = __floats2half2_rn(tile[4 * vc + 0][wl],
                                             tile[4 * vc + 1][wl]);
        const __half2 p1 = __floats2half2_rn(tile[4 * vc + 2][wl],
                                             tile[4 * vc + 3][wl]);
        uint2 o;
        o.x = *reinterpret_cast<const unsigned*>(&p0);
        o.y = *reinterpret_cast<const unsigned*>(&p1);
        *reinterpret_cast<uint2*>(
            g_OTh + (size_t)(w0 + wl) * VD + v0 + 4 * vc) = o;
    }
}

// ---------------------------------------------------------------------------
// Kernel B: score. One block (128 thr = 4 warps) per b. No smem, no barriers.
// Warp wid owns k = wid+4i (7 predicated slots). dv + all word ids + ALL
// row loads batched up front (MLP=7, rows are 8B uint2 so regs stay ~36).
// ---------------------------------------------------------------------------
__global__ __launch_bounds__(VD)
void score_kernel(const int* __restrict__ tnids,
                  float* __restrict__ out) {
    const int b    = blockIdx.x;
    const int t    = threadIdx.x;
    const int lane = t & 31;
    const int wid  = t >> 5;

    const float4 dv =
        __ldg(reinterpret_cast<const float4*>(g_dg + (size_t)b * VD) + lane);

    int words[NSLOT];
#pragma unroll
    for (int i = 0; i < NSLOT; i++) {
        const int k = wid + 4 * i;
        words[i] = (k < KNUM) ? __ldg(&tnids[b * KNUM + k]) : 0;
    }

    uint2 rows[NSLOT];
#pragma unroll
    for (int i = 0; i < NSLOT; i++) {
        const int k = wid + 4 * i;
        if (k < KNUM) {
            rows[i] = *reinterpret_cast<const uint2*>(
                          g_OTh + (size_t)words[i] * VD + 4 * lane);
        }
    }

#pragma unroll
    for (int i = 0; i < NSLOT; i++) {
        const int k = wid + 4 * i;
        if (k < KNUM) {
            const __half2 h0 = *reinterpret_cast<const __half2*>(&rows[i].x);
            const __half2 h1 = *reinterpret_cast<const __half2*>(&rows[i].y);
            const float2 f0 = __half22float2(h0);
            const float2 f1 = __half22float2(h1);
            float s = dv.x * f0.x + dv.y * f0.y + dv.z * f1.x + dv.w * f1.y;
            s += __shfl_xor_sync(0xffffffffu, s, 16);
            s += __shfl_xor_sync(0xffffffffu, s, 8);
            s += __shfl_xor_sync(0xffffffffu, s, 4);
            s += __shfl_xor_sync(0xffffffffu, s, 2);
            s += __shfl_xor_sync(0xffffffffu, s, 1);
            if (lane == 0) out[b * KNUM + k] = s;
        }
    }
}

// ---------------------------------------------------------------------------
// Inputs (metadata order): context_ids[B] i32 (unused), doc_ids[B] i32,
// target_noise_ids[B*K] i32, D[NUM_DOCS*VD] f32, O[VD*NW] f32.
// Output: out[B*K] f32.
// ---------------------------------------------------------------------------
extern "C" void kernel_launch(void* const* d_in, const int* in_sizes, int n_in,
                              void* d_out, int out_size) {
    const int*   doc_ids = (const int*)d_in[1];
    const int*   tnids   = (const int*)d_in[2];
    const float* D       = (const float*)d_in[3];
    const float* O       = (const float*)d_in[4];
    float*       out     = (float*)d_out;

    prep_kernel<<<NBLK, 256>>>(doc_ids, D, O);
    score_kernel<<<BATCH, VD>>>(tnids, out);
}

// round 11
// speedup vs baseline: 1.4980x; 1.1860x over previous
#include <cuda_runtime.h>
#include <cuda_fp16.h>
#include <cstddef>

#define NW    100000
#define VD    128
#define BATCH 16384
#define KNUM  26
#define NPAIR 13   // k-pairs; warp wid owns p = wid + 4*i, i = 0..3
#define NPW   4

#define GB     512                 // gather blocks (256 thr, 8 warps x 4 b)
#define TBX    (NW / 32)           // 3125
#define TBY    (VD / 32)           // 4
#define NBLK   (GB + TBX * TBY)    // fused grid

// Scratch (static device globals; no allocation):
//   g_OTh: 25.6 MB fp16 transposed O, OTh[word][v]
//   g_dgh: 4 MB   fp16 gathered doc vectors, dgh[b][v]
__device__ __half g_OTh[(size_t)NW * VD];
__device__ __half g_dgh[(size_t)BATCH * VD];

// ---------------------------------------------------------------------------
// Kernel A (fused): blocks [0, GB) gather dgh[b] = fp16(D[doc_ids[b]]) with
// 4 b's per warp (MLP=4); blocks [GB, ...) transpose O [VD, NW] f32 ->
// OTh [NW, VD] fp16, tiled 32x32 via smem. Gather blocks lead the grid so
// their latency overlaps the DRAM-bound transpose.
// ---------------------------------------------------------------------------
__global__ __launch_bounds__(256)
void prep_kernel(const int* __restrict__ doc_ids,
                 const float* __restrict__ D,
                 const float* __restrict__ O) {
    const int t = threadIdx.x;

    if (blockIdx.x < GB) {
        // ---- gather partition ----
        const int warp = t >> 5;
        const int lane = t & 31;
        const int b0   = (blockIdx.x * 8 + warp) * 4;

        int doc[4];
#pragma unroll
        for (int i = 0; i < 4; i++) doc[i] = __ldg(&doc_ids[b0 + i]);

        float4 v[4];
#pragma unroll
        for (int i = 0; i < 4; i++) {
            v[i] = __ldg(reinterpret_cast<const float4*>(
                             D + (size_t)doc[i] * VD) + lane);
        }
#pragma unroll
        for (int i = 0; i < 4; i++) {
            const __half2 p0 = __floats2half2_rn(v[i].x, v[i].y);
            const __half2 p1 = __floats2half2_rn(v[i].z, v[i].w);
            uint2 o;
            o.x = *reinterpret_cast<const unsigned*>(&p0);
            o.y = *reinterpret_cast<const unsigned*>(&p1);
            *reinterpret_cast<uint2*>(
                g_dgh + (size_t)(b0 + i) * VD + 4 * lane) = o;
        }
        return;
    }

    // ---- transpose partition ----
    const int idx = blockIdx.x - GB;
    const int w0  = (idx % TBX) * 32;
    const int v0  = (idx / TBX) * 32;

    __shared__ float tile[32][33];

    {   // read: thread (ty = v_local, tx = w-float4-chunk), coalesced along w
        const int ty = t >> 3;
        const int tx = t & 7;
        const float4 f = __ldg(reinterpret_cast<const float4*>(
                                   O + (size_t)(v0 + ty) * NW + w0) + tx);
        tile[ty][4 * tx + 0] = f.x;
        tile[ty][4 * tx + 1] = f.y;
        tile[ty][4 * tx + 2] = f.z;
        tile[ty][4 * tx + 3] = f.w;
    }
    __syncthreads();

    {   // write: thread (wl = w_local, vc = v-quad) -> 4 halves (8B)
        const int wl = t >> 3;
        const int vc = t & 7;
        const __half2 p0 = __floats2half2_rn(tile[4 * vc + 0][wl],
                                             tile[4 * vc + 1][wl]);
        const __half2 p1 = __floats2half2_rn(tile[4 * vc + 2][wl],
                                             tile[4 * vc + 3][wl]);
        uint2 o;
        o.x = *reinterpret_cast<const unsigned*>(&p0);
        o.y = *reinterpret_cast<const unsigned*>(&p1);
        *reinterpret_cast<uint2*>(
            g_OTh + (size_t)(w0 + wl) * VD + v0 + 4 * vc) = o;
    }
}

// ---------------------------------------------------------------------------
// Kernel B: score. One block (128 thr = 4 warps) per b. No smem, no barriers.
// Half-warp layout: lanes 0-15 own k=2p, lanes 16-31 own k=2p+1; each lane
// covers 8 v-elements (uint4 = 4x half2). Warp wid owns pairs p = wid+4i
// (4 slots, warp-uniform predication). Dot = 1 HMUL2 + 3 HFMA2; cross-lane
// reduce = 4 shuffles shared by TWO scores. All loads batched (MLP=4).
// ---------------------------------------------------------------------------
__global__ __launch_bounds__(VD)
void score_kernel(const int* __restrict__ tnids,
                  float* __restrict__ out) {
    const int b    = blockIdx.x;
    const int t    = threadIdx.x;
    const int lane = t & 31;
    const int wid  = t >> 5;
    const int half = lane >> 4;   // 0: k=2p, 1: k=2p+1
    const int sub  = lane & 15;   // v = 8*sub .. 8*sub+7

    // doc vector chunk (fp16, 8 halves): address depends only on (b, sub)
    const uint4 dbits = *reinterpret_cast<const uint4*>(
                            g_dgh + (size_t)b * VD + 8 * sub);
    const __half2 d0 = *reinterpret_cast<const __half2*>(&dbits.x);
    const __half2 d1 = *reinterpret_cast<const __half2*>(&dbits.y);
    const __half2 d2 = *reinterpret_cast<const __half2*>(&dbits.z);
    const __half2 d3 = *reinterpret_cast<const __half2*>(&dbits.w);

    // word ids (2 distinct addresses per warp -> 1 wavefront each, batched)
    int words[NPW];
#pragma unroll
    for (int i = 0; i < NPW; i++) {
        const int p = wid + 4 * i;
        words[i] = (p < NPAIR) ? __ldg(&tnids[b * KNUM + 2 * p + half]) : 0;
    }

    // OT rows, batched (MLP=4): one LDG.128 per slot per lane
    uint4 rows[NPW];
#pragma unroll
    for (int i = 0; i < NPW; i++) {
        const int p = wid + 4 * i;
        if (p < NPAIR) {
            rows[i] = *reinterpret_cast<const uint4*>(
                          g_OTh + (size_t)words[i] * VD + 8 * sub);
        }
    }

#pragma unroll
    for (int i = 0; i < NPW; i++) {
        const int p = wid + 4 * i;           // warp-uniform
        if (p < NPAIR) {
            const __half2 r0 = *reinterpret_cast<const __half2*>(&rows[i].x);
            const __half2 r1 = *reinterpret_cast<const __half2*>(&rows[i].y);
            const __half2 r2 = *reinterpret_cast<const __half2*>(&rows[i].z);
            const __half2 r3 = *reinterpret_cast<const __half2*>(&rows[i].w);
            __half2 acc = __hmul2(r0, d0);
            acc = __hfma2(r1, d1, acc);
            acc = __hfma2(r2, d2, acc);
            acc = __hfma2(r3, d3, acc);
            const float2 f = __half22float2(acc);
            float s = f.x + f.y;
            s += __shfl_xor_sync(0xffffffffu, s, 8);
            s += __shfl_xor_sync(0xffffffffu, s, 4);
            s += __shfl_xor_sync(0xffffffffu, s, 2);
            s += __shfl_xor_sync(0xffffffffu, s, 1);
            if (sub == 0) out[b * KNUM + 2 * p + half] = s;  // lanes 0, 16
        }
    }
}

// ---------------------------------------------------------------------------
// Inputs (metadata order): context_ids[B] i32 (unused), doc_ids[B] i32,
// target_noise_ids[B*K] i32, D[NUM_DOCS*VD] f32, O[VD*NW] f32.
// Output: out[B*K] f32.
// ---------------------------------------------------------------------------
extern "C" void kernel_launch(void* const* d_in, const int* in_sizes, int n_in,
                              void* d_out, int out_size) {
    const int*   doc_ids = (const int*)d_in[1];
    const int*   tnids   = (const int*)d_in[2];
    const float* D       = (const float*)d_in[3];
    const float* O       = (const float*)d_in[4];
    float*       out     = (float*)d_out;

    prep_kernel<<<NBLK, 256>>>(doc_ids, D, O);
    score_kernel<<<BATCH, VD>>>(tnids, out);
}

// round 12
// speedup vs baseline: 1.4995x; 1.0010x over previous
#include <cuda_runtime.h>
#include <cuda_fp16.h>
#include <cstddef>

#define NW    100000
#define VD    128
#define BATCH 16384
#define KNUM  26
#define NPAIR 13   // k-pairs; warp (wid&3) owns p = (wid&3) + 4*i, i = 0..3
#define NPW   4
#define BPB   2    // batch elements per score block

#define GB     512                 // gather blocks (256 thr, 8 warps x 4 b)
#define TBX    (NW / 32)           // 3125
#define TBY    (VD / 32)           // 4
#define NBLK   (GB + TBX * TBY)    // fused prep grid

// Scratch (static device globals; no allocation):
//   g_OTh: 25.6 MB fp16 transposed O, OTh[word][v]
//   g_dgh: 4 MB   fp16 gathered doc vectors, dgh[b][v]
__device__ __half g_OTh[(size_t)NW * VD];
__device__ __half g_dgh[(size_t)BATCH * VD];

// ---------------------------------------------------------------------------
// Kernel A (fused): blocks [0, GB) gather dgh[b] = fp16(D[doc_ids[b]]) with
// 4 b's per warp (MLP=4); blocks [GB, ...) transpose O [VD, NW] f32 ->
// OTh [NW, VD] fp16, tiled 32x32 via smem. Gather blocks lead the grid so
// their latency overlaps the DRAM-bound transpose.
// ---------------------------------------------------------------------------
__global__ __launch_bounds__(256)
void prep_kernel(const int* __restrict__ doc_ids,
                 const float* __restrict__ D,
                 const float* __restrict__ O) {
    const int t = threadIdx.x;

    if (blockIdx.x < GB) {
        // ---- gather partition ----
        const int warp = t >> 5;
        const int lane = t & 31;
        const int b0   = (blockIdx.x * 8 + warp) * 4;

        int doc[4];
#pragma unroll
        for (int i = 0; i < 4; i++) doc[i] = __ldg(&doc_ids[b0 + i]);

        float4 v[4];
#pragma unroll
        for (int i = 0; i < 4; i++) {
            v[i] = __ldg(reinterpret_cast<const float4*>(
                             D + (size_t)doc[i] * VD) + lane);
        }
#pragma unroll
        for (int i = 0; i < 4; i++) {
            const __half2 p0 = __floats2half2_rn(v[i].x, v[i].y);
            const __half2 p1 = __floats2half2_rn(v[i].z, v[i].w);
            uint2 o;
            o.x = *reinterpret_cast<const unsigned*>(&p0);
            o.y = *reinterpret_cast<const unsigned*>(&p1);
            *reinterpret_cast<uint2*>(
                g_dgh + (size_t)(b0 + i) * VD + 4 * lane) = o;
        }
        return;
    }

    // ---- transpose partition ----
    const int idx = blockIdx.x - GB;
    const int w0  = (idx % TBX) * 32;
    const int v0  = (idx / TBX) * 32;

    __shared__ float tile[32][33];

    {   // read: thread (ty = v_local, tx = w-float4-chunk), coalesced along w
        const int ty = t >> 3;
        const int tx = t & 7;
        const float4 f = __ldg(reinterpret_cast<const float4*>(
                                   O + (size_t)(v0 + ty) * NW + w0) + tx);
        tile[ty][4 * tx + 0] = f.x;
        tile[ty][4 * tx + 1] = f.y;
        tile[ty][4 * tx + 2] = f.z;
        tile[ty][4 * tx + 3] = f.w;
    }
    __syncthreads();

    {   // write: thread (wl = w_local, vc = v-quad) -> 4 halves (8B)
        const int wl = t >> 3;
        const int vc = t & 7;
        const __half2 p0 = __floats2half2_rn(tile[4 * vc + 0][wl],
                                             tile[4 * vc + 1][wl]);
        const __half2 p1 = __floats2half2_rn(tile[4 * vc + 2][wl],
                                             tile[4 * vc + 3][wl]);
        uint2 o;
        o.x = *reinterpret_cast<const unsigned*>(&p0);
        o.y = *reinterpret_cast<const unsigned*>(&p1);
        *reinterpret_cast<uint2*>(
            g_OTh + (size_t)(w0 + wl) * VD + v0 + 4 * vc) = o;
    }
}

// ---------------------------------------------------------------------------
// Kernel B: score. 256-thread blocks, 2 batch elements per block:
// warps 0-3 -> b0, warps 4-7 -> b0+1 (identical per-warp body to R11).
// Half-warp layout: lanes 0-15 own k=2p, lanes 16-31 own k=2p+1; each lane
// covers 8 v-elements (uint4 = 4x half2). Warp w4 = wid&3 owns pairs
// p = w4 + 4i (warp-uniform predication). Dot = 1 HMUL2 + 3 HFMA2;
// cross-lane reduce = 4 shuffles shared by TWO scores. Loads batched (MLP=4).
// ---------------------------------------------------------------------------
__global__ __launch_bounds__(32 * 8)
void score_kernel(const int* __restrict__ tnids,
                  float* __restrict__ out) {
    const int t    = threadIdx.x;
    const int lane = t & 31;
    const int wid  = t >> 5;
    const int w4   = wid & 3;
    const int b    = blockIdx.x * BPB + (wid >> 2);
    const int half = lane >> 4;   // 0: k=2p, 1: k=2p+1
    const int sub  = lane & 15;   // v = 8*sub .. 8*sub+7

    // doc vector chunk (fp16, 8 halves): address depends only on (b, sub)
    const uint4 dbits = __ldg(reinterpret_cast<const uint4*>(
                                  g_dgh + (size_t)b * VD + 8 * sub));
    const __half2 d0 = *reinterpret_cast<const __half2*>(&dbits.x);
    const __half2 d1 = *reinterpret_cast<const __half2*>(&dbits.y);
    const __half2 d2 = *reinterpret_cast<const __half2*>(&dbits.z);
    const __half2 d3 = *reinterpret_cast<const __half2*>(&dbits.w);

    // word ids (2 distinct addresses per warp -> broadcast, batched)
    int words[NPW];
#pragma unroll
    for (int i = 0; i < NPW; i++) {
        const int p = w4 + 4 * i;
        words[i] = (p < NPAIR) ? __ldg(&tnids[b * KNUM + 2 * p + half]) : 0;
    }

    // OT rows, batched (MLP=4): one LDG.128 per slot per lane
    uint4 rows[NPW];
#pragma unroll
    for (int i = 0; i < NPW; i++) {
        const int p = w4 + 4 * i;
        if (p < NPAIR) {
            rows[i] = __ldg(reinterpret_cast<const uint4*>(
                                g_OTh + (size_t)words[i] * VD + 8 * sub));
        }
    }

#pragma unroll
    for (int i = 0; i < NPW; i++) {
        const int p = w4 + 4 * i;            // warp-uniform
        if (p < NPAIR) {
            const __half2 r0 = *reinterpret_cast<const __half2*>(&rows[i].x);
            const __half2 r1 = *reinterpret_cast<const __half2*>(&rows[i].y);
            const __half2 r2 = *reinterpret_cast<const __half2*>(&rows[i].z);
            const __half2 r3 = *reinterpret_cast<const __half2*>(&rows[i].w);
            __half2 acc = __hmul2(r0, d0);
            acc = __hfma2(r1, d1, acc);
            acc = __hfma2(r2, d2, acc);
            acc = __hfma2(r3, d3, acc);
            const float2 f = __half22float2(acc);
            float s = f.x + f.y;
            s += __shfl_xor_sync(0xffffffffu, s, 8);
            s += __shfl_xor_sync(0xffffffffu, s, 4);
            s += __shfl_xor_sync(0xffffffffu, s, 2);
            s += __shfl_xor_sync(0xffffffffu, s, 1);
            if (sub == 0) out[b * KNUM + 2 * p + half] = s;  // lanes 0, 16
        }
    }
}

// ---------------------------------------------------------------------------
// Inputs (metadata order): context_ids[B] i32 (unused), doc_ids[B] i32,
// target_noise_ids[B*K] i32, D[NUM_DOCS*VD] f32, O[VD*NW] f32.
// Output: out[B*K] f32.
// ---------------------------------------------------------------------------
extern "C" void kernel_launch(void* const* d_in, const int* in_sizes, int n_in,
                              void* d_out, int out_size) {
    const int*   doc_ids = (const int*)d_in[1];
    const int*   tnids   = (const int*)d_in[2];
    const float* D       = (const float*)d_in[3];
    const float* O       = (const float*)d_in[4];
    float*       out     = (float*)d_out;

    prep_kernel<<<NBLK, 256>>>(doc_ids, D, O);
    score_kernel<<<BATCH / BPB, 256>>>(tnids, out);
}